// round 7
// baseline (speedup 1.0000x reference)
#include <cuda_runtime.h>
#include <cstdint>

#define N_NODES 50000
#define N_EDGES 600000
#define N_GRAPHS 512
#define DIM 128
#define N_FEAT 78
#define N_LAYERS 4
#define BN_EPS 1e-5f

typedef unsigned long long ull;

// ---------------- scratch (device globals; no allocation allowed) ----------
__device__ float g_u[2][(size_t)N_NODES * DIM];  // ping-pong node features
__device__ float g_acc[(size_t)N_NODES * DIM];   // layer-conv accumulator
__device__ float g_stats[2 * DIM];               // BN sums / sumsq
__device__ float g_norm[2 * DIM];                // sc[128], sh[128]
__device__ int   g_deg[N_NODES];
__device__ int   g_ptr[N_NODES + 1];
__device__ int   g_cur[N_NODES];
__device__ int   g_csr[N_EDGES];                 // src sorted by dst

// ---------------- f32x2 packed-FMA helpers (FFMA2) -------------------------
__device__ __forceinline__ void fma2(ull& d, ull a, ull b) {
    asm("fma.rn.f32x2 %0, %1, %2, %0;" : "+l"(d) : "l"(a), "l"(b));
}
__device__ __forceinline__ ull bcast2(float x) {
    unsigned u = __float_as_uint(x);
    ull r; asm("mov.b64 %0, {%1, %1};" : "=l"(r) : "r"(u)); return r;
}
__device__ __forceinline__ ull pack2(float x, float y) {
    ull r; asm("mov.b64 %0, {%1, %2};" : "=l"(r)
               : "r"(__float_as_uint(x)), "r"(__float_as_uint(y))); return r;
}
__device__ __forceinline__ float2 unpack2(ull v) {
    unsigned lo, hi;
    asm("mov.b64 {%0, %1}, %2;" : "=r"(lo), "=r"(hi) : "l"(v));
    return make_float2(__uint_as_float(lo), __uint_as_float(hi));
}

// ---------------- 128x128 GEMM micro-kernel, 8x8 thread tile ---------------
// 256 threads: ty = tid>>4 (16 row groups of 8), tx = tid&15 (8-col groups).
template <int KMAX, int APAD>
__device__ __forceinline__ void mma8(const float* __restrict__ sA,
                                     const float* __restrict__ sW,
                                     ull acc[8][4], int ty, int c0) {
    #pragma unroll 2
    for (int kk = 0; kk < KMAX; kk += 4) {
        float a[8][4];
        #pragma unroll
        for (int i = 0; i < 8; i++)
            *(float4*)a[i] = *(const float4*)&sA[(ty * 8 + i) * APAD + kk];
        #pragma unroll
        for (int k = 0; k < 4; k++) {
            const ulonglong2* wp = (const ulonglong2*)&sW[(kk + k) * DIM + c0];
            ulonglong2 w01 = wp[0], w23 = wp[1];
            #pragma unroll
            for (int i = 0; i < 8; i++) {
                ull av = bcast2(a[i][k]);
                fma2(acc[i][0], av, w01.x); fma2(acc[i][1], av, w01.y);
                fma2(acc[i][2], av, w23.x); fma2(acc[i][3], av, w23.y);
            }
        }
    }
}

#define TM 128                 // rows per block
#define NT 256                 // threads per block
#define ZPAD 132
#define WREG 16384             // floats for one 128x128 weight matrix
#define SMEM_GIN ((WREG + TM * ZPAD) * (int)sizeof(float))
#define XPAD 80
#define XOFF (N_FEAT * DIM)    // X tile starts after W1 in region A
#define INI_A (N_FEAT * DIM + TM * XPAD)   // 9984 + 10240 = 20224 floats
#define SMEM_INI ((INI_A + TM * ZPAD) * (int)sizeof(float))

// ---------------- CSR build --------------------------------------------------
__global__ void init_kernel(float* __restrict__ out) {
    int i = blockIdx.x * blockDim.x + threadIdx.x;
    if (i < N_NODES) g_deg[i] = 0;
    if (i < N_GRAPHS * DIM) out[i] = 0.0f;
}

__global__ void count_kernel(const int* __restrict__ ei) {
    int e = blockIdx.x * blockDim.x + threadIdx.x;
    if (e < N_EDGES) atomicAdd(&g_deg[__ldg(&ei[N_EDGES + e])], 1);
}

__global__ void scan_kernel() {
    __shared__ int ssum[1024];
    const int t = threadIdx.x;
    const int CH = (N_NODES + 1023) / 1024;   // 49
    const int base = t * CH;
    int sum = 0;
    for (int i = 0; i < CH; i++) {
        int idx = base + i;
        if (idx < N_NODES) sum += g_deg[idx];
    }
    ssum[t] = sum;
    __syncthreads();
    for (int off = 1; off < 1024; off <<= 1) {
        int v = (t >= off) ? ssum[t - off] : 0;
        __syncthreads();
        ssum[t] += v;
        __syncthreads();
    }
    int run = ssum[t] - sum;
    for (int i = 0; i < CH; i++) {
        int idx = base + i;
        if (idx < N_NODES) {
            g_ptr[idx] = run;
            g_cur[idx] = run;
            run += g_deg[idx];
        }
    }
    if (t == 0) g_ptr[N_NODES] = N_EDGES;
}

__global__ void fill_kernel(const int* __restrict__ ei) {
    int e = blockIdx.x * blockDim.x + threadIdx.x;
    if (e >= N_EDGES) return;
    int dst = __ldg(&ei[N_EDGES + e]);
    int pos = atomicAdd(&g_cur[dst], 1);
    g_csr[pos] = __ldg(&ei[e]);
}

// ---------------- ini embed: u0 = relu(x@W1+b1)@W2+b2 ----------------------
__global__ void __launch_bounds__(NT, 1)
ini_gemm_kernel(const float* __restrict__ x,
                const float* __restrict__ w1, const float* __restrict__ b1,
                const float* __restrict__ w2, const float* __restrict__ b2) {
    extern __shared__ float sm[];
    float* sW = sm;                 // region A: W1 then X (stage1), W2 (stage2)
    float* sT = sm + INI_A;         // region B: T tile
    const int tid = threadIdx.x;
    const int rbase = blockIdx.x * TM;

    for (int i = tid * 4; i < N_FEAT * DIM; i += NT * 4)
        *(float4*)&sW[i] = *(const float4*)&w1[i];
    for (int i = tid; i < TM * XPAD; i += NT) {
        int r = i / XPAD, c = i - r * XPAD;
        sW[XOFF + i] = (c < N_FEAT && rbase + r < N_NODES)
                       ? x[(size_t)(rbase + r) * N_FEAT + c] : 0.0f;
    }
    __syncthreads();

    const int ty = tid >> 4, tx = tid & 15, c0 = tx << 3;
    ull acc[8][4];

    // ---- stage 1: T = relu(x @ W1 + b1) ----
    {
        ull b[4];
        #pragma unroll
        for (int j = 0; j < 4; j++)
            b[j] = pack2(b1[c0 + 2 * j], b1[c0 + 2 * j + 1]);
        #pragma unroll
        for (int i = 0; i < 8; i++)
            #pragma unroll
            for (int j = 0; j < 4; j++) acc[i][j] = b[j];
    }
    mma8<XPAD, XPAD>(sW + XOFF, sW, acc, ty, c0);
    __syncthreads();

    #pragma unroll
    for (int i = 0; i < 8; i++)
        #pragma unroll
        for (int j = 0; j < 4; j++) {
            float2 f = unpack2(acc[i][j]);
            sT[(ty * 8 + i) * ZPAD + c0 + 2 * j]     = fmaxf(f.x, 0.0f);
            sT[(ty * 8 + i) * ZPAD + c0 + 2 * j + 1] = fmaxf(f.y, 0.0f);
        }
    for (int i = tid * 4; i < DIM * DIM; i += NT * 4)
        *(float4*)&sW[i] = *(const float4*)&w2[i];
    __syncthreads();

    // ---- stage 2: U = T @ W2 + b2 (no relu) ----
    {
        ull b[4];
        #pragma unroll
        for (int j = 0; j < 4; j++)
            b[j] = pack2(b2[c0 + 2 * j], b2[c0 + 2 * j + 1]);
        #pragma unroll
        for (int i = 0; i < 8; i++)
            #pragma unroll
            for (int j = 0; j < 4; j++) acc[i][j] = b[j];
    }
    mma8<DIM, ZPAD>(sT, sW, acc, ty, c0);

    #pragma unroll
    for (int i = 0; i < 8; i++) {
        int r = rbase + ty * 8 + i;
        if (r < N_NODES) {
            float2 f0 = unpack2(acc[i][0]), f1 = unpack2(acc[i][1]);
            float2 f2 = unpack2(acc[i][2]), f3 = unpack2(acc[i][3]);
            *(float4*)&g_u[0][(size_t)r * DIM + c0] =
                make_float4(f0.x, f0.y, f1.x, f1.y);
            *(float4*)&g_u[0][(size_t)r * DIM + c0 + 4] =
                make_float4(f2.x, f2.y, f3.x, f3.y);
        }
    }
}

// ---------------- prep: compute sc/sh, zero stats (1 block) ----------------
__global__ void prep_kernel(const float* __restrict__ gamma,
                            const float* __restrict__ beta, int layer) {
    int c = threadIdx.x;   // 128 threads
    float sc, sh;
    if (layer == 0) { sc = 1.0f; sh = 0.0f; }
    else {
        float mean = g_stats[c] * (1.0f / N_NODES);
        float var  = g_stats[DIM + c] * (1.0f / N_NODES) - mean * mean;
        sc = rsqrtf(var + BN_EPS) * gamma[c];
        sh = beta[c] - mean * sc;
    }
    g_norm[c] = sc;
    g_norm[DIM + c] = sh;
    g_stats[c] = 0.0f;
    g_stats[DIM + c] = 0.0f;
}

// ---------------- GIN layer: fused gather + BN + acc + MLP + stats ---------
__global__ void __launch_bounds__(NT, 1)
gin_gemm_kernel(const float* __restrict__ w1, const float* __restrict__ b1,
                const float* __restrict__ w2, const float* __restrict__ b2,
                const float* __restrict__ lwp, const float* __restrict__ lbp,
                int layer, int rd) {
    extern __shared__ float sm[];
    float* sW = sm;
    float* sZ = sm + WREG;
    const int tid = threadIdx.x;
    const int rbase = blockIdx.x * TM;
    const float* __restrict__ uin = g_u[rd];
    float* __restrict__ uout = g_u[rd ^ 1];

    for (int i = tid * 4; i < DIM * DIM; i += NT * 4)
        *(float4*)&sW[i] = *(const float4*)&w1[i];
    const float lw_prev = (layer > 0) ? __ldg(&lwp[layer - 1]) : 0.0f;
    const float lb = __ldg(lbp);

    // fused gather: z = sc*(u_node + sum u_src) + (deg+1)*sh; acc += lw*h
    {
        const int wid = tid >> 5, lane = tid & 31, cc = lane << 2;
        float4 scv = *(const float4*)&g_norm[cc];
        float4 shv = *(const float4*)&g_norm[DIM + cc];
        #pragma unroll 1
        for (int rr = 0; rr < 16; rr++) {
            int r = (wid << 4) + rr;                 // 8 warps x 16 rows = 128
            int node = rbase + r;
            float4 z4 = make_float4(0, 0, 0, 0);
            if (node < N_NODES) {
                float4 un = *(const float4*)&uin[(size_t)node * DIM + cc];
                int p0 = __ldg(&g_ptr[node]), p1 = __ldg(&g_ptr[node + 1]);
                float4 s0 = un, s1 = make_float4(0, 0, 0, 0);
                float4 s2 = make_float4(0, 0, 0, 0), s3 = make_float4(0, 0, 0, 0);
                int k = p0;
                for (; k + 4 <= p1; k += 4) {
                    int sa = __ldg(&g_csr[k]),      sb = __ldg(&g_csr[k + 1]);
                    int sc2 = __ldg(&g_csr[k + 2]), sd = __ldg(&g_csr[k + 3]);
                    float4 ua = *(const float4*)&uin[(size_t)sa * DIM + cc];
                    float4 ub = *(const float4*)&uin[(size_t)sb * DIM + cc];
                    float4 uc = *(const float4*)&uin[(size_t)sc2 * DIM + cc];
                    float4 ud = *(const float4*)&uin[(size_t)sd * DIM + cc];
                    s0.x += ua.x; s0.y += ua.y; s0.z += ua.z; s0.w += ua.w;
                    s1.x += ub.x; s1.y += ub.y; s1.z += ub.z; s1.w += ub.w;
                    s2.x += uc.x; s2.y += uc.y; s2.z += uc.z; s2.w += uc.w;
                    s3.x += ud.x; s3.y += ud.y; s3.z += ud.z; s3.w += ud.w;
                }
                for (; k < p1; k++) {
                    int sa = __ldg(&g_csr[k]);
                    float4 ua = *(const float4*)&uin[(size_t)sa * DIM + cc];
                    s0.x += ua.x; s0.y += ua.y; s0.z += ua.z; s0.w += ua.w;
                }
                s0.x += s1.x + s2.x + s3.x; s0.y += s1.y + s2.y + s3.y;
                s0.z += s1.z + s2.z + s3.z; s0.w += s1.w + s2.w + s3.w;
                float dp1 = (float)(p1 - p0 + 1);
                z4.x = fmaf(scv.x, s0.x, dp1 * shv.x);
                z4.y = fmaf(scv.y, s0.y, dp1 * shv.y);
                z4.z = fmaf(scv.z, s0.z, dp1 * shv.z);
                z4.w = fmaf(scv.w, s0.w, dp1 * shv.w);
                if (layer > 0) {
                    float4 h;
                    h.x = fmaf(un.x, scv.x, shv.x);
                    h.y = fmaf(un.y, scv.y, shv.y);
                    h.z = fmaf(un.z, scv.z, shv.z);
                    h.w = fmaf(un.w, scv.w, shv.w);
                    float4 a;
                    if (layer == 1) a = make_float4(lb, lb, lb, lb);
                    else a = *(const float4*)&g_acc[(size_t)node * DIM + cc];
                    a.x = fmaf(lw_prev, h.x, a.x); a.y = fmaf(lw_prev, h.y, a.y);
                    a.z = fmaf(lw_prev, h.z, a.z); a.w = fmaf(lw_prev, h.w, a.w);
                    *(float4*)&g_acc[(size_t)node * DIM + cc] = a;
                }
            }
            *(float4*)&sZ[r * ZPAD + cc] = z4;
        }
    }
    __syncthreads();

    const int ty = tid >> 4, tx = tid & 15, c0 = tx << 3;
    ull acc[8][4];

    // ---- stage 1: T = relu(z @ W1 + b1) ----
    {
        ull b[4];
        #pragma unroll
        for (int j = 0; j < 4; j++)
            b[j] = pack2(b1[c0 + 2 * j], b1[c0 + 2 * j + 1]);
        #pragma unroll
        for (int i = 0; i < 8; i++)
            #pragma unroll
            for (int j = 0; j < 4; j++) acc[i][j] = b[j];
    }
    mma8<DIM, ZPAD>(sZ, sW, acc, ty, c0);
    __syncthreads();

    #pragma unroll
    for (int i = 0; i < 8; i++)
        #pragma unroll
        for (int j = 0; j < 4; j++) {
            float2 f = unpack2(acc[i][j]);
            sZ[(ty * 8 + i) * ZPAD + c0 + 2 * j]     = fmaxf(f.x, 0.0f);
            sZ[(ty * 8 + i) * ZPAD + c0 + 2 * j + 1] = fmaxf(f.y, 0.0f);
        }
    for (int i = tid * 4; i < DIM * DIM; i += NT * 4)
        *(float4*)&sW[i] = *(const float4*)&w2[i];
    __syncthreads();

    // ---- stage 2: u_next = relu(T @ W2 + b2) ----
    {
        ull b[4];
        #pragma unroll
        for (int j = 0; j < 4; j++)
            b[j] = pack2(b2[c0 + 2 * j], b2[c0 + 2 * j + 1]);
        #pragma unroll
        for (int i = 0; i < 8; i++)
            #pragma unroll
            for (int j = 0; j < 4; j++) acc[i][j] = b[j];
    }
    mma8<DIM, ZPAD>(sZ, sW, acc, ty, c0);
    __syncthreads();   // sZ reads done; reuse for stats partials

    float csum[8], csum2[8];
    #pragma unroll
    for (int j = 0; j < 8; j++) { csum[j] = 0.0f; csum2[j] = 0.0f; }
    #pragma unroll
    for (int i = 0; i < 8; i++) {
        int r = rbase + ty * 8 + i;
        float2 f0 = unpack2(acc[i][0]), f1 = unpack2(acc[i][1]);
        float2 f2 = unpack2(acc[i][2]), f3 = unpack2(acc[i][3]);
        float o[8] = { fmaxf(f0.x, 0.f), fmaxf(f0.y, 0.f),
                       fmaxf(f1.x, 0.f), fmaxf(f1.y, 0.f),
                       fmaxf(f2.x, 0.f), fmaxf(f2.y, 0.f),
                       fmaxf(f3.x, 0.f), fmaxf(f3.y, 0.f) };
        if (r < N_NODES) {
            *(float4*)&uout[(size_t)r * DIM + c0] =
                make_float4(o[0], o[1], o[2], o[3]);
            *(float4*)&uout[(size_t)r * DIM + c0 + 4] =
                make_float4(o[4], o[5], o[6], o[7]);
            #pragma unroll
            for (int j = 0; j < 8; j++) {
                csum[j] += o[j];
                csum2[j] += o[j] * o[j];
            }
        }
    }
    float* ps  = sZ;           // 16 x 128
    float* ps2 = sZ + 2048;    // 16 x 128
    #pragma unroll
    for (int j = 0; j < 8; j++) {
        ps [ty * DIM + c0 + j] = csum[j];
        ps2[ty * DIM + c0 + j] = csum2[j];
    }
    __syncthreads();
    {
        int col = tid & (DIM - 1), kind = tid >> 7;
        const float* base = kind ? ps2 : ps;
        float tot = 0.0f;
        #pragma unroll
        for (int t = 0; t < 16; t++) tot += base[t * DIM + col];
        atomicAdd(&g_stats[kind * DIM + col], tot);
    }
}

// ---------------- final: BN(u3) + layer-conv + pool -------------------------
__global__ void final_kernel(const float* __restrict__ gamma,
                             const float* __restrict__ beta,
                             const float* __restrict__ lwp,
                             const int* __restrict__ batch,
                             float* __restrict__ out, int rd) {
    __shared__ float sSc[DIM], sSh[DIM];
    const int tid = threadIdx.x;
    if (tid < DIM) {
        float mean = g_stats[tid] * (1.0f / N_NODES);
        float var  = g_stats[DIM + tid] * (1.0f / N_NODES) - mean * mean;
        float sc = rsqrtf(var + BN_EPS) * gamma[tid];
        sSc[tid] = sc;
        sSh[tid] = beta[tid] - mean * sc;
    }
    __syncthreads();
    int gw = (blockIdx.x * blockDim.x + tid) >> 5;
    if (gw >= N_NODES) return;
    int lane = tid & 31, c4 = lane << 2;
    float lw3 = __ldg(&lwp[N_LAYERS - 1]);
    float4 u = *(const float4*)&g_u[rd][(size_t)gw * DIM + c4];
    float4 a = *(const float4*)&g_acc[(size_t)gw * DIM + c4];
    float4 h;
    h.x = fmaf(u.x, sSc[c4],     sSh[c4]);
    h.y = fmaf(u.y, sSc[c4 + 1], sSh[c4 + 1]);
    h.z = fmaf(u.z, sSc[c4 + 2], sSh[c4 + 2]);
    h.w = fmaf(u.w, sSc[c4 + 3], sSh[c4 + 3]);
    a.x = fmaf(lw3, h.x, a.x); a.y = fmaf(lw3, h.y, a.y);
    a.z = fmaf(lw3, h.z, a.z); a.w = fmaf(lw3, h.w, a.w);
    int b = __ldg(&batch[gw]);
    float* p = &out[b * DIM + c4];
    asm volatile("red.global.add.v4.f32 [%0], {%1,%2,%3,%4};"
                 :: "l"(p), "f"(a.x), "f"(a.y), "f"(a.z), "f"(a.w) : "memory");
}

// ---------------- launch ----------------------------------------------------
extern "C" void kernel_launch(void* const* d_in, const int* in_sizes, int n_in,
                              void* d_out, int out_size) {
    const float* x     = (const float*)d_in[0];
    const int*   ei    = (const int*)  d_in[1];
    const int*   batch = (const int*)  d_in[2];
    const float* iw1   = (const float*)d_in[3];
    const float* ib1   = (const float*)d_in[4];
    const float* iw2   = (const float*)d_in[5];
    const float* ib2   = (const float*)d_in[6];
    const float* gw1   = (const float*)d_in[7];
    const float* gb1   = (const float*)d_in[8];
    const float* gw2   = (const float*)d_in[9];
    const float* gb2   = (const float*)d_in[10];
    const float* gamma = (const float*)d_in[11];
    const float* beta  = (const float*)d_in[12];
    const float* lw    = (const float*)d_in[13];
    const float* lb    = (const float*)d_in[14];
    float* out = (float*)d_out;

    cudaFuncSetAttribute(ini_gemm_kernel,
                         cudaFuncAttributeMaxDynamicSharedMemorySize, SMEM_INI);
    cudaFuncSetAttribute(gin_gemm_kernel,
                         cudaFuncAttributeMaxDynamicSharedMemorySize, SMEM_GIN);

    const int gemm_blocks = (N_NODES + TM - 1) / TM;    // 391
    const int fin_blocks  = N_NODES * 32 / 256;         // 6250

    init_kernel<<<(N_GRAPHS * DIM + 255) / 256, 256>>>(out);     // 1
    count_kernel<<<(N_EDGES + 255) / 256, 256>>>(ei);            // 2
    scan_kernel<<<1, 1024>>>();                                  // 3
    ini_gemm_kernel<<<gemm_blocks, NT, SMEM_INI>>>(              // 4 (profiled)
        x, iw1, ib1, iw2, ib2);
    fill_kernel<<<(N_EDGES + 255) / 256, 256>>>(ei);             // 5

    for (int l = 0; l < N_LAYERS; l++) {
        const float* gm = gamma + (size_t)(l > 0 ? l - 1 : 0) * DIM;
        const float* bt = beta  + (size_t)(l > 0 ? l - 1 : 0) * DIM;
        prep_kernel<<<1, 128>>>(gm, bt, l);
        gin_gemm_kernel<<<gemm_blocks, NT, SMEM_GIN>>>(
            gw1 + (size_t)l * DIM * DIM, gb1 + (size_t)l * DIM,
            gw2 + (size_t)l * DIM * DIM, gb2 + (size_t)l * DIM,
            lw, lb, l, l & 1);
    }

    final_kernel<<<fin_blocks, 256>>>(gamma + (size_t)(N_LAYERS - 1) * DIM,
                                      beta + (size_t)(N_LAYERS - 1) * DIM,
                                      lw, batch, out, 0);
}

// round 8
// speedup vs baseline: 1.0092x; 1.0092x over previous
#include <cuda_runtime.h>
#include <cstdint>

#define N_NODES 50000
#define N_EDGES 600000
#define N_GRAPHS 512
#define DIM 128
#define N_FEAT 78
#define N_LAYERS 4
#define BN_EPS 1e-5f

typedef unsigned long long ull;

// ---------------- scratch (device globals; no allocation allowed) ----------
__device__ float g_u[2][(size_t)N_NODES * DIM];  // ping-pong node features
__device__ float g_acc[(size_t)N_NODES * DIM];   // layer-conv accumulator
__device__ float g_stats[2 * DIM];               // BN sums / sumsq
__device__ float g_norm[2 * DIM];                // sc[128], sh[128]
__device__ int   g_deg[N_NODES];
__device__ int   g_ptr[N_NODES + 1];
__device__ int   g_cur[N_NODES];
__device__ int   g_csr[N_EDGES];                 // src sorted by dst

// ---------------- f32x2 packed-FMA helpers (FFMA2) -------------------------
__device__ __forceinline__ void fma2(ull& d, ull a, ull b) {
    asm("fma.rn.f32x2 %0, %1, %2, %0;" : "+l"(d) : "l"(a), "l"(b));
}
__device__ __forceinline__ ull bcast2(float x) {
    unsigned u = __float_as_uint(x);
    ull r; asm("mov.b64 %0, {%1, %1};" : "=l"(r) : "r"(u)); return r;
}
__device__ __forceinline__ ull pack2(float x, float y) {
    ull r; asm("mov.b64 %0, {%1, %2};" : "=l"(r)
               : "r"(__float_as_uint(x)), "r"(__float_as_uint(y))); return r;
}
__device__ __forceinline__ float2 unpack2(ull v) {
    unsigned lo, hi;
    asm("mov.b64 {%0, %1}, %2;" : "=r"(lo), "=r"(hi) : "l"(v));
    return make_float2(__uint_as_float(lo), __uint_as_float(hi));
}

// ---------------- pipelined 64x128 GEMM micro-kernel, 8x8 tile -------------
// 128 threads: ty = tid>>4 (8 row groups of 8), tx = tid&15 (8-col groups).
__device__ __forceinline__ void compute4(const float a[8][4],
                                         const float* __restrict__ sW,
                                         ull acc[8][4], int kk, int c0) {
    ulonglong2 w[4][2];
    #pragma unroll
    for (int k = 0; k < 4; k++) {
        const ulonglong2* wp = (const ulonglong2*)&sW[(kk + k) * DIM + c0];
        w[k][0] = wp[0]; w[k][1] = wp[1];
    }
    #pragma unroll
    for (int k = 0; k < 4; k++)
        #pragma unroll
        for (int i = 0; i < 8; i++) {
            ull av = bcast2(a[i][k]);
            fma2(acc[i][0], av, w[k][0].x); fma2(acc[i][1], av, w[k][0].y);
            fma2(acc[i][2], av, w[k][1].x); fma2(acc[i][3], av, w[k][1].y);
        }
}

template <int KMAX, int APAD>
__device__ __forceinline__ void mma8(const float* __restrict__ sA,
                                     const float* __restrict__ sW,
                                     ull acc[8][4], int ty, int c0) {
    float a0[8][4], a1[8][4];
    #pragma unroll
    for (int i = 0; i < 8; i++)
        *(float4*)a0[i] = *(const float4*)&sA[(ty * 8 + i) * APAD];
    #pragma unroll
    for (int kk = 0; kk < KMAX; kk += 8) {
        #pragma unroll
        for (int i = 0; i < 8; i++)
            *(float4*)a1[i] = *(const float4*)&sA[(ty * 8 + i) * APAD + kk + 4];
        compute4(a0, sW, acc, kk, c0);
        if (kk + 8 < KMAX) {
            #pragma unroll
            for (int i = 0; i < 8; i++)
                *(float4*)a0[i] =
                    *(const float4*)&sA[(ty * 8 + i) * APAD + kk + 8];
        }
        compute4(a1, sW, acc, kk + 4, c0);
    }
}

#define ZPAD 132
#define WREG 16384
#define SMEM_BYTES ((WREG + 64 * ZPAD) * (int)sizeof(float))
#define XPAD 80
#define XOFF (N_FEAT * DIM)
#define NT 128

// ---------------- CSR build --------------------------------------------------
__global__ void init_kernel(float* __restrict__ out) {
    int i = blockIdx.x * blockDim.x + threadIdx.x;
    if (i < N_NODES) g_deg[i] = 0;
    if (i < N_GRAPHS * DIM) out[i] = 0.0f;
}

__global__ void count_kernel(const int* __restrict__ ei) {
    int e = blockIdx.x * blockDim.x + threadIdx.x;
    if (e < N_EDGES) atomicAdd(&g_deg[__ldg(&ei[N_EDGES + e])], 1);
}

__global__ void scan_kernel() {
    __shared__ int ssum[1024];
    const int t = threadIdx.x;
    const int CH = (N_NODES + 1023) / 1024;   // 49
    const int base = t * CH;
    int sum = 0;
    for (int i = 0; i < CH; i++) {
        int idx = base + i;
        if (idx < N_NODES) sum += g_deg[idx];
    }
    ssum[t] = sum;
    __syncthreads();
    for (int off = 1; off < 1024; off <<= 1) {
        int v = (t >= off) ? ssum[t - off] : 0;
        __syncthreads();
        ssum[t] += v;
        __syncthreads();
    }
    int run = ssum[t] - sum;
    for (int i = 0; i < CH; i++) {
        int idx = base + i;
        if (idx < N_NODES) {
            g_ptr[idx] = run;
            g_cur[idx] = run;
            run += g_deg[idx];
        }
    }
    if (t == 0) g_ptr[N_NODES] = N_EDGES;
}

__global__ void fill_kernel(const int* __restrict__ ei) {
    int e = blockIdx.x * blockDim.x + threadIdx.x;
    if (e >= N_EDGES) return;
    int dst = __ldg(&ei[N_EDGES + e]);
    int pos = atomicAdd(&g_cur[dst], 1);
    g_csr[pos] = __ldg(&ei[e]);
}

// ---------------- ini embed: u0 = relu(x@W1+b1)@W2+b2 ----------------------
__global__ void __launch_bounds__(NT, 2)
ini_gemm_kernel(const float* __restrict__ x,
                const float* __restrict__ w1, const float* __restrict__ b1,
                const float* __restrict__ w2, const float* __restrict__ b2) {
    extern __shared__ float sm[];
    float* sW = sm;
    float* sT = sm + WREG;
    const int tid = threadIdx.x;
    const int rbase = blockIdx.x * 64;

    for (int i = tid * 4; i < N_FEAT * DIM; i += NT * 4)
        *(float4*)&sW[i] = *(const float4*)&w1[i];
    for (int i = tid; i < 64 * XPAD; i += NT) {
        int r = i / XPAD, c = i - r * XPAD;
        sW[XOFF + i] = (c < N_FEAT && rbase + r < N_NODES)
                       ? x[(size_t)(rbase + r) * N_FEAT + c] : 0.0f;
    }
    __syncthreads();

    const int ty = tid >> 4, tx = tid & 15, c0 = tx << 3;
    ull acc[8][4];

    // ---- stage 1: T = relu(x @ W1 + b1) ----
    {
        ull b[4];
        #pragma unroll
        for (int j = 0; j < 4; j++)
            b[j] = pack2(b1[c0 + 2 * j], b1[c0 + 2 * j + 1]);
        #pragma unroll
        for (int i = 0; i < 8; i++)
            #pragma unroll
            for (int j = 0; j < 4; j++) acc[i][j] = b[j];
    }
    mma8<XPAD, XPAD>(sW + XOFF, sW, acc, ty, c0);
    __syncthreads();

    #pragma unroll
    for (int i = 0; i < 8; i++)
        #pragma unroll
        for (int j = 0; j < 4; j++) {
            float2 f = unpack2(acc[i][j]);
            sT[(ty * 8 + i) * ZPAD + c0 + 2 * j]     = fmaxf(f.x, 0.0f);
            sT[(ty * 8 + i) * ZPAD + c0 + 2 * j + 1] = fmaxf(f.y, 0.0f);
        }
    for (int i = tid * 4; i < DIM * DIM; i += NT * 4)
        *(float4*)&sW[i] = *(const float4*)&w2[i];
    __syncthreads();

    // ---- stage 2: U = T @ W2 + b2 (no relu) ----
    {
        ull b[4];
        #pragma unroll
        for (int j = 0; j < 4; j++)
            b[j] = pack2(b2[c0 + 2 * j], b2[c0 + 2 * j + 1]);
        #pragma unroll
        for (int i = 0; i < 8; i++)
            #pragma unroll
            for (int j = 0; j < 4; j++) acc[i][j] = b[j];
    }
    mma8<DIM, ZPAD>(sT, sW, acc, ty, c0);

    #pragma unroll
    for (int i = 0; i < 8; i++) {
        int r = rbase + ty * 8 + i;
        if (r < N_NODES) {
            float2 f0 = unpack2(acc[i][0]), f1 = unpack2(acc[i][1]);
            float2 f2 = unpack2(acc[i][2]), f3 = unpack2(acc[i][3]);
            *(float4*)&g_u[0][(size_t)r * DIM + c0] =
                make_float4(f0.x, f0.y, f1.x, f1.y);
            *(float4*)&g_u[0][(size_t)r * DIM + c0 + 4] =
                make_float4(f2.x, f2.y, f3.x, f3.y);
        }
    }
}

// ---------------- prep: compute sc/sh, zero stats (1 block) ----------------
__global__ void prep_kernel(const float* __restrict__ gamma,
                            const float* __restrict__ beta, int layer) {
    int c = threadIdx.x;   // 128 threads
    float sc, sh;
    if (layer == 0) { sc = 1.0f; sh = 0.0f; }
    else {
        float mean = g_stats[c] * (1.0f / N_NODES);
        float var  = g_stats[DIM + c] * (1.0f / N_NODES) - mean * mean;
        sc = rsqrtf(var + BN_EPS) * gamma[c];
        sh = beta[c] - mean * sc;
    }
    g_norm[c] = sc;
    g_norm[DIM + c] = sh;
    g_stats[c] = 0.0f;
    g_stats[DIM + c] = 0.0f;
}

// ---------------- GIN layer: fused gather + BN + acc + MLP + stats ---------
__global__ void __launch_bounds__(NT, 2)
gin_gemm_kernel(const float* __restrict__ w1, const float* __restrict__ b1,
                const float* __restrict__ w2, const float* __restrict__ b2,
                const float* __restrict__ lwp, const float* __restrict__ lbp,
                int layer, int rd) {
    extern __shared__ float sm[];
    float* sW = sm;
    float* sZ = sm + WREG;
    const int tid = threadIdx.x;
    const int rbase = blockIdx.x * 64;
    const float* __restrict__ uin = g_u[rd];
    float* __restrict__ uout = g_u[rd ^ 1];

    for (int i = tid * 4; i < DIM * DIM; i += NT * 4)
        *(float4*)&sW[i] = *(const float4*)&w1[i];
    const float lw_prev = (layer > 0) ? __ldg(&lwp[layer - 1]) : 0.0f;
    const float lb = __ldg(lbp);

    // fused gather: z = sc*(u_node + sum u_src) + (deg+1)*sh; acc += lw*h
    {
        const int wid = tid >> 5, lane = tid & 31, cc = lane << 2;
        float4 scv = *(const float4*)&g_norm[cc];
        float4 shv = *(const float4*)&g_norm[DIM + cc];
        #pragma unroll 1
        for (int rr = 0; rr < 16; rr++) {
            int r = (wid << 4) + rr;
            int node = rbase + r;
            float4 z4 = make_float4(0, 0, 0, 0);
            if (node < N_NODES) {
                float4 un = *(const float4*)&uin[(size_t)node * DIM + cc];
                int p0 = __ldg(&g_ptr[node]), p1 = __ldg(&g_ptr[node + 1]);
                float4 s0 = un, s1 = make_float4(0, 0, 0, 0);
                float4 s2 = make_float4(0, 0, 0, 0), s3 = make_float4(0, 0, 0, 0);
                int k = p0;
                for (; k + 4 <= p1; k += 4) {
                    int sa = __ldg(&g_csr[k]),      sb = __ldg(&g_csr[k + 1]);
                    int sc2 = __ldg(&g_csr[k + 2]), sd = __ldg(&g_csr[k + 3]);
                    float4 ua = *(const float4*)&uin[(size_t)sa * DIM + cc];
                    float4 ub = *(const float4*)&uin[(size_t)sb * DIM + cc];
                    float4 uc = *(const float4*)&uin[(size_t)sc2 * DIM + cc];
                    float4 ud = *(const float4*)&uin[(size_t)sd * DIM + cc];
                    s0.x += ua.x; s0.y += ua.y; s0.z += ua.z; s0.w += ua.w;
                    s1.x += ub.x; s1.y += ub.y; s1.z += ub.z; s1.w += ub.w;
                    s2.x += uc.x; s2.y += uc.y; s2.z += uc.z; s2.w += uc.w;
                    s3.x += ud.x; s3.y += ud.y; s3.z += ud.z; s3.w += ud.w;
                }
                for (; k < p1; k++) {
                    int sa = __ldg(&g_csr[k]);
                    float4 ua = *(const float4*)&uin[(size_t)sa * DIM + cc];
                    s0.x += ua.x; s0.y += ua.y; s0.z += ua.z; s0.w += ua.w;
                }
                s0.x += s1.x + s2.x + s3.x; s0.y += s1.y + s2.y + s3.y;
                s0.z += s1.z + s2.z + s3.z; s0.w += s1.w + s2.w + s3.w;
                float dp1 = (float)(p1 - p0 + 1);
                z4.x = fmaf(scv.x, s0.x, dp1 * shv.x);
                z4.y = fmaf(scv.y, s0.y, dp1 * shv.y);
                z4.z = fmaf(scv.z, s0.z, dp1 * shv.z);
                z4.w = fmaf(scv.w, s0.w, dp1 * shv.w);
                if (layer > 0) {
                    float4 h;
                    h.x = fmaf(un.x, scv.x, shv.x);
                    h.y = fmaf(un.y, scv.y, shv.y);
                    h.z = fmaf(un.z, scv.z, shv.z);
                    h.w = fmaf(un.w, scv.w, shv.w);
                    float4 a;
                    if (layer == 1) a = make_float4(lb, lb, lb, lb);
                    else a = *(const float4*)&g_acc[(size_t)node * DIM + cc];
                    a.x = fmaf(lw_prev, h.x, a.x); a.y = fmaf(lw_prev, h.y, a.y);
                    a.z = fmaf(lw_prev, h.z, a.z); a.w = fmaf(lw_prev, h.w, a.w);
                    *(float4*)&g_acc[(size_t)node * DIM + cc] = a;
                }
            }
            *(float4*)&sZ[r * ZPAD + cc] = z4;
        }
    }
    __syncthreads();

    const int ty = tid >> 4, tx = tid & 15, c0 = tx << 3;
    ull acc[8][4];

    // ---- stage 1: T = relu(z @ W1 + b1) ----
    {
        ull b[4];
        #pragma unroll
        for (int j = 0; j < 4; j++)
            b[j] = pack2(b1[c0 + 2 * j], b1[c0 + 2 * j + 1]);
        #pragma unroll
        for (int i = 0; i < 8; i++)
            #pragma unroll
            for (int j = 0; j < 4; j++) acc[i][j] = b[j];
    }
    mma8<DIM, ZPAD>(sZ, sW, acc, ty, c0);
    __syncthreads();

    #pragma unroll
    for (int i = 0; i < 8; i++)
        #pragma unroll
        for (int j = 0; j < 4; j++) {
            float2 f = unpack2(acc[i][j]);
            sZ[(ty * 8 + i) * ZPAD + c0 + 2 * j]     = fmaxf(f.x, 0.0f);
            sZ[(ty * 8 + i) * ZPAD + c0 + 2 * j + 1] = fmaxf(f.y, 0.0f);
        }
    for (int i = tid * 4; i < DIM * DIM; i += NT * 4)
        *(float4*)&sW[i] = *(const float4*)&w2[i];
    __syncthreads();

    // ---- stage 2: u_next = relu(T @ W2 + b2) ----
    {
        ull b[4];
        #pragma unroll
        for (int j = 0; j < 4; j++)
            b[j] = pack2(b2[c0 + 2 * j], b2[c0 + 2 * j + 1]);
        #pragma unroll
        for (int i = 0; i < 8; i++)
            #pragma unroll
            for (int j = 0; j < 4; j++) acc[i][j] = b[j];
    }
    mma8<DIM, ZPAD>(sZ, sW, acc, ty, c0);
    __syncthreads();   // sZ reads done; reuse for stats partials

    float csum[8], csum2[8];
    #pragma unroll
    for (int j = 0; j < 8; j++) { csum[j] = 0.0f; csum2[j] = 0.0f; }
    #pragma unroll
    for (int i = 0; i < 8; i++) {
        int r = rbase + ty * 8 + i;
        float2 f0 = unpack2(acc[i][0]), f1 = unpack2(acc[i][1]);
        float2 f2 = unpack2(acc[i][2]), f3 = unpack2(acc[i][3]);
        float o[8] = { fmaxf(f0.x, 0.f), fmaxf(f0.y, 0.f),
                       fmaxf(f1.x, 0.f), fmaxf(f1.y, 0.f),
                       fmaxf(f2.x, 0.f), fmaxf(f2.y, 0.f),
                       fmaxf(f3.x, 0.f), fmaxf(f3.y, 0.f) };
        if (r < N_NODES) {
            *(float4*)&uout[(size_t)r * DIM + c0] =
                make_float4(o[0], o[1], o[2], o[3]);
            *(float4*)&uout[(size_t)r * DIM + c0 + 4] =
                make_float4(o[4], o[5], o[6], o[7]);
            #pragma unroll
            for (int j = 0; j < 8; j++) {
                csum[j] += o[j];
                csum2[j] += o[j] * o[j];
            }
        }
    }
    float* ps  = sZ;           // 8 x 128
    float* ps2 = sZ + 1024;    // 8 x 128
    #pragma unroll
    for (int j = 0; j < 8; j++) {
        ps [ty * DIM + c0 + j] = csum[j];
        ps2[ty * DIM + c0 + j] = csum2[j];
    }
    __syncthreads();
    {
        int col = tid;   // 128 threads, one column each, both kinds
        float t1 = 0.0f, t2 = 0.0f;
        #pragma unroll
        for (int t = 0; t < 8; t++) {
            t1 += ps [t * DIM + col];
            t2 += ps2[t * DIM + col];
        }
        atomicAdd(&g_stats[col], t1);
        atomicAdd(&g_stats[DIM + col], t2);
    }
}

// ---------------- final: BN(u3) + layer-conv + pool -------------------------
__global__ void final_kernel(const float* __restrict__ gamma,
                             const float* __restrict__ beta,
                             const float* __restrict__ lwp,
                             const int* __restrict__ batch,
                             float* __restrict__ out, int rd) {
    __shared__ float sSc[DIM], sSh[DIM];
    const int tid = threadIdx.x;
    if (tid < DIM) {
        float mean = g_stats[tid] * (1.0f / N_NODES);
        float var  = g_stats[DIM + tid] * (1.0f / N_NODES) - mean * mean;
        float sc = rsqrtf(var + BN_EPS) * gamma[tid];
        sSc[tid] = sc;
        sSh[tid] = beta[tid] - mean * sc;
    }
    __syncthreads();
    int gw = (blockIdx.x * blockDim.x + tid) >> 5;
    if (gw >= N_NODES) return;
    int lane = tid & 31, c4 = lane << 2;
    float lw3 = __ldg(&lwp[N_LAYERS - 1]);
    float4 u = *(const float4*)&g_u[rd][(size_t)gw * DIM + c4];
    float4 a = *(const float4*)&g_acc[(size_t)gw * DIM + c4];
    float4 h;
    h.x = fmaf(u.x, sSc[c4],     sSh[c4]);
    h.y = fmaf(u.y, sSc[c4 + 1], sSh[c4 + 1]);
    h.z = fmaf(u.z, sSc[c4 + 2], sSh[c4 + 2]);
    h.w = fmaf(u.w, sSc[c4 + 3], sSh[c4 + 3]);
    a.x = fmaf(lw3, h.x, a.x); a.y = fmaf(lw3, h.y, a.y);
    a.z = fmaf(lw3, h.z, a.z); a.w = fmaf(lw3, h.w, a.w);
    int b = __ldg(&batch[gw]);
    float* p = &out[b * DIM + c4];
    asm volatile("red.global.add.v4.f32 [%0], {%1,%2,%3,%4};"
                 :: "l"(p), "f"(a.x), "f"(a.y), "f"(a.z), "f"(a.w) : "memory");
}

// ---------------- launch ----------------------------------------------------
extern "C" void kernel_launch(void* const* d_in, const int* in_sizes, int n_in,
                              void* d_out, int out_size) {
    const float* x     = (const float*)d_in[0];
    const int*   ei    = (const int*)  d_in[1];
    const int*   batch = (const int*)  d_in[2];
    const float* iw1   = (const float*)d_in[3];
    const float* ib1   = (const float*)d_in[4];
    const float* iw2   = (const float*)d_in[5];
    const float* ib2   = (const float*)d_in[6];
    const float* gw1   = (const float*)d_in[7];
    const float* gb1   = (const float*)d_in[8];
    const float* gw2   = (const float*)d_in[9];
    const float* gb2   = (const float*)d_in[10];
    const float* gamma = (const float*)d_in[11];
    const float* beta  = (const float*)d_in[12];
    const float* lw    = (const float*)d_in[13];
    const float* lb    = (const float*)d_in[14];
    float* out = (float*)d_out;

    cudaFuncSetAttribute(ini_gemm_kernel,
                         cudaFuncAttributeMaxDynamicSharedMemorySize, SMEM_BYTES);
    cudaFuncSetAttribute(gin_gemm_kernel,
                         cudaFuncAttributeMaxDynamicSharedMemorySize, SMEM_BYTES);

    const int gemm_blocks = (N_NODES + 63) / 64;        // 782
    const int fin_blocks  = N_NODES * 32 / 256;         // 6250

    init_kernel<<<(N_GRAPHS * DIM + 255) / 256, 256>>>(out);     // 1
    count_kernel<<<(N_EDGES + 255) / 256, 256>>>(ei);            // 2
    scan_kernel<<<1, 1024>>>();                                  // 3
    ini_gemm_kernel<<<gemm_blocks, NT, SMEM_BYTES>>>(            // 4 (profiled)
        x, iw1, ib1, iw2, ib2);
    fill_kernel<<<(N_EDGES + 255) / 256, 256>>>(ei);             // 5

    for (int l = 0; l < N_LAYERS; l++) {
        const float* gm = gamma + (size_t)(l > 0 ? l - 1 : 0) * DIM;
        const float* bt = beta  + (size_t)(l > 0 ? l - 1 : 0) * DIM;
        prep_kernel<<<1, 128>>>(gm, bt, l);
        gin_gemm_kernel<<<gemm_blocks, NT, SMEM_BYTES>>>(
            gw1 + (size_t)l * DIM * DIM, gb1 + (size_t)l * DIM,
            gw2 + (size_t)l * DIM * DIM, gb2 + (size_t)l * DIM,
            lw, lb, l, l & 1);
    }

    final_kernel<<<fin_blocks, 256>>>(gamma + (size_t)(N_LAYERS - 1) * DIM,
                                      beta + (size_t)(N_LAYERS - 1) * DIM,
                                      lw, batch, out, 0);
}

// round 9
// speedup vs baseline: 1.3302x; 1.3180x over previous
#include <cuda_runtime.h>
#include <cstdint>

#define N_NODES 50000
#define N_EDGES 600000
#define N_GRAPHS 512
#define DIM 128
#define N_FEAT 78
#define N_LAYERS 4
#define BN_EPS 1e-5f

typedef unsigned long long ull;

// ---------------- scratch (device globals; no allocation allowed) ----------
__device__ float g_u[2][(size_t)N_NODES * DIM];  // ping-pong node features
__device__ float g_z[(size_t)N_NODES * DIM];     // gathered GIN input
__device__ float g_acc[(size_t)N_NODES * DIM];   // layer-conv accumulator
__device__ float g_stats[2 * DIM];               // BN sums / sumsq
__device__ float g_norm[2 * DIM];                // sc[128], sh[128]
__device__ int   g_deg[N_NODES];
__device__ int   g_ptr[N_NODES + 1];
__device__ int   g_cur[N_NODES];
__device__ int   g_csr[N_EDGES];                 // src sorted by dst

// ---------------- f32x2 packed-FMA helpers (FFMA2) -------------------------
__device__ __forceinline__ void fma2(ull& d, ull a, ull b) {
    asm("fma.rn.f32x2 %0, %1, %2, %0;" : "+l"(d) : "l"(a), "l"(b));
}
__device__ __forceinline__ ull bcast2(float x) {
    unsigned u = __float_as_uint(x);
    ull r; asm("mov.b64 %0, {%1, %1};" : "=l"(r) : "r"(u)); return r;
}
__device__ __forceinline__ ull pack2(float x, float y) {
    ull r; asm("mov.b64 %0, {%1, %2};" : "=l"(r)
               : "r"(__float_as_uint(x)), "r"(__float_as_uint(y))); return r;
}
__device__ __forceinline__ float2 unpack2(ull v) {
    unsigned lo, hi;
    asm("mov.b64 {%0, %1}, %2;" : "=r"(lo), "=r"(hi) : "l"(v));
    return make_float2(__uint_as_float(lo), __uint_as_float(hi));
}

// ---------------- 64x128 GEMM micro-kernel, 8x8 thread tile (round-6) ------
// 128 threads: ty = tid>>4 (8 row groups of 8), tx = tid&15 (8-col groups).
template <int KMAX, int APAD>
__device__ __forceinline__ void mma8(const float* __restrict__ sA,
                                     const float* __restrict__ sW,
                                     ull acc[8][4], int ty, int c0) {
    #pragma unroll 2
    for (int kk = 0; kk < KMAX; kk += 4) {
        float a[8][4];
        #pragma unroll
        for (int i = 0; i < 8; i++)
            *(float4*)a[i] = *(const float4*)&sA[(ty * 8 + i) * APAD + kk];
        #pragma unroll
        for (int k = 0; k < 4; k++) {
            const ulonglong2* wp = (const ulonglong2*)&sW[(kk + k) * DIM + c0];
            ulonglong2 w01 = wp[0], w23 = wp[1];
            #pragma unroll
            for (int i = 0; i < 8; i++) {
                ull av = bcast2(a[i][k]);
                fma2(acc[i][0], av, w01.x); fma2(acc[i][1], av, w01.y);
                fma2(acc[i][2], av, w23.x); fma2(acc[i][3], av, w23.y);
            }
        }
    }
}

#define ZPAD 132
#define WREG 16384
#define SMEM_BYTES ((WREG + 64 * ZPAD) * (int)sizeof(float))
#define XPAD 80
#define XOFF (N_FEAT * DIM)
#define NT 128

// ---------------- CSR build --------------------------------------------------
__global__ void init_kernel(float* __restrict__ out) {
    int i = blockIdx.x * blockDim.x + threadIdx.x;
    if (i < N_NODES) g_deg[i] = 0;
    if (i < N_GRAPHS * DIM) out[i] = 0.0f;
}

__global__ void count_kernel(const int* __restrict__ ei) {
    int e = blockIdx.x * blockDim.x + threadIdx.x;
    if (e < N_EDGES) atomicAdd(&g_deg[__ldg(&ei[N_EDGES + e])], 1);
}

__global__ void scan_kernel() {
    __shared__ int ssum[1024];
    const int t = threadIdx.x;
    const int CH = (N_NODES + 1023) / 1024;   // 49
    const int base = t * CH;
    int sum = 0;
    for (int i = 0; i < CH; i++) {
        int idx = base + i;
        if (idx < N_NODES) sum += g_deg[idx];
    }
    ssum[t] = sum;
    __syncthreads();
    for (int off = 1; off < 1024; off <<= 1) {
        int v = (t >= off) ? ssum[t - off] : 0;
        __syncthreads();
        ssum[t] += v;
        __syncthreads();
    }
    int run = ssum[t] - sum;
    for (int i = 0; i < CH; i++) {
        int idx = base + i;
        if (idx < N_NODES) {
            g_ptr[idx] = run;
            g_cur[idx] = run;
            run += g_deg[idx];
        }
    }
    if (t == 0) g_ptr[N_NODES] = N_EDGES;
}

__global__ void fill_kernel(const int* __restrict__ ei) {
    int e = blockIdx.x * blockDim.x + threadIdx.x;
    if (e >= N_EDGES) return;
    int dst = __ldg(&ei[N_EDGES + e]);
    int pos = atomicAdd(&g_cur[dst], 1);
    g_csr[pos] = __ldg(&ei[e]);
}

// ---------------- ini embed: u0 = relu(x@W1+b1)@W2+b2 ----------------------
__global__ void __launch_bounds__(NT, 2)
ini_gemm_kernel(const float* __restrict__ x,
                const float* __restrict__ w1, const float* __restrict__ b1,
                const float* __restrict__ w2, const float* __restrict__ b2) {
    extern __shared__ float sm[];
    float* sW = sm;
    float* sT = sm + WREG;
    const int tid = threadIdx.x;
    const int rbase = blockIdx.x * 64;

    for (int i = tid * 4; i < N_FEAT * DIM; i += NT * 4)
        *(float4*)&sW[i] = *(const float4*)&w1[i];
    for (int i = tid; i < 64 * XPAD; i += NT) {
        int r = i / XPAD, c = i - r * XPAD;
        sW[XOFF + i] = (c < N_FEAT && rbase + r < N_NODES)
                       ? x[(size_t)(rbase + r) * N_FEAT + c] : 0.0f;
    }
    __syncthreads();

    const int ty = tid >> 4, tx = tid & 15, c0 = tx << 3;
    ull acc[8][4];

    // ---- stage 1: T = relu(x @ W1 + b1) ----
    {
        ull b[4];
        #pragma unroll
        for (int j = 0; j < 4; j++)
            b[j] = pack2(b1[c0 + 2 * j], b1[c0 + 2 * j + 1]);
        #pragma unroll
        for (int i = 0; i < 8; i++)
            #pragma unroll
            for (int j = 0; j < 4; j++) acc[i][j] = b[j];
    }
    mma8<XPAD, XPAD>(sW + XOFF, sW, acc, ty, c0);
    __syncthreads();

    #pragma unroll
    for (int i = 0; i < 8; i++)
        #pragma unroll
        for (int j = 0; j < 4; j++) {
            float2 f = unpack2(acc[i][j]);
            sT[(ty * 8 + i) * ZPAD + c0 + 2 * j]     = fmaxf(f.x, 0.0f);
            sT[(ty * 8 + i) * ZPAD + c0 + 2 * j + 1] = fmaxf(f.y, 0.0f);
        }
    for (int i = tid * 4; i < DIM * DIM; i += NT * 4)
        *(float4*)&sW[i] = *(const float4*)&w2[i];
    __syncthreads();

    // ---- stage 2: U = T @ W2 + b2 (no relu) ----
    {
        ull b[4];
        #pragma unroll
        for (int j = 0; j < 4; j++)
            b[j] = pack2(b2[c0 + 2 * j], b2[c0 + 2 * j + 1]);
        #pragma unroll
        for (int i = 0; i < 8; i++)
            #pragma unroll
            for (int j = 0; j < 4; j++) acc[i][j] = b[j];
    }
    mma8<DIM, ZPAD>(sT, sW, acc, ty, c0);

    #pragma unroll
    for (int i = 0; i < 8; i++) {
        int r = rbase + ty * 8 + i;
        if (r < N_NODES) {
            float2 f0 = unpack2(acc[i][0]), f1 = unpack2(acc[i][1]);
            float2 f2 = unpack2(acc[i][2]), f3 = unpack2(acc[i][3]);
            *(float4*)&g_u[0][(size_t)r * DIM + c0] =
                make_float4(f0.x, f0.y, f1.x, f1.y);
            *(float4*)&g_u[0][(size_t)r * DIM + c0 + 4] =
                make_float4(f2.x, f2.y, f3.x, f3.y);
        }
    }
}

// ---------------- prep: compute sc/sh, zero stats (1 block) ----------------
__global__ void prep_kernel(const float* __restrict__ gamma,
                            const float* __restrict__ beta, int layer) {
    int c = threadIdx.x;   // 128 threads
    float sc, sh;
    if (layer == 0) { sc = 1.0f; sh = 0.0f; }
    else {
        float mean = g_stats[c] * (1.0f / N_NODES);
        float var  = g_stats[DIM + c] * (1.0f / N_NODES) - mean * mean;
        sc = rsqrtf(var + BN_EPS) * gamma[c];
        sh = beta[c] - mean * sc;
    }
    g_norm[c] = sc;
    g_norm[DIM + c] = sh;
    g_stats[c] = 0.0f;
    g_stats[DIM + c] = 0.0f;
}

// ---------------- gather: z = sc*(u+sum u_src)+(deg+1)*sh; acc += lw*h -----
// 1 warp per node, no smem -> full occupancy, L2-bandwidth bound.
__global__ void __launch_bounds__(256)
gather_kernel(const float* __restrict__ lwp, const float* __restrict__ lbp,
              int layer, int rd) {
    int node = (blockIdx.x * blockDim.x + threadIdx.x) >> 5;
    if (node >= N_NODES) return;
    const float* __restrict__ uin = g_u[rd];
    const int lane = threadIdx.x & 31, cc = lane << 2;
    float4 scv = *(const float4*)&g_norm[cc];
    float4 shv = *(const float4*)&g_norm[DIM + cc];
    float4 un = *(const float4*)&uin[(size_t)node * DIM + cc];
    int p0 = __ldg(&g_ptr[node]), p1 = __ldg(&g_ptr[node + 1]);
    float4 s0 = un, s1 = make_float4(0, 0, 0, 0);
    float4 s2 = make_float4(0, 0, 0, 0), s3 = make_float4(0, 0, 0, 0);
    int k = p0;
    for (; k + 4 <= p1; k += 4) {
        int sa = __ldg(&g_csr[k]),      sb = __ldg(&g_csr[k + 1]);
        int sc2 = __ldg(&g_csr[k + 2]), sd = __ldg(&g_csr[k + 3]);
        float4 ua = *(const float4*)&uin[(size_t)sa * DIM + cc];
        float4 ub = *(const float4*)&uin[(size_t)sb * DIM + cc];
        float4 uc = *(const float4*)&uin[(size_t)sc2 * DIM + cc];
        float4 ud = *(const float4*)&uin[(size_t)sd * DIM + cc];
        s0.x += ua.x; s0.y += ua.y; s0.z += ua.z; s0.w += ua.w;
        s1.x += ub.x; s1.y += ub.y; s1.z += ub.z; s1.w += ub.w;
        s2.x += uc.x; s2.y += uc.y; s2.z += uc.z; s2.w += uc.w;
        s3.x += ud.x; s3.y += ud.y; s3.z += ud.z; s3.w += ud.w;
    }
    for (; k < p1; k++) {
        int sa = __ldg(&g_csr[k]);
        float4 ua = *(const float4*)&uin[(size_t)sa * DIM + cc];
        s0.x += ua.x; s0.y += ua.y; s0.z += ua.z; s0.w += ua.w;
    }
    s0.x += s1.x + s2.x + s3.x; s0.y += s1.y + s2.y + s3.y;
    s0.z += s1.z + s2.z + s3.z; s0.w += s1.w + s2.w + s3.w;
    float dp1 = (float)(p1 - p0 + 1);
    float4 z4;
    z4.x = fmaf(scv.x, s0.x, dp1 * shv.x);
    z4.y = fmaf(scv.y, s0.y, dp1 * shv.y);
    z4.z = fmaf(scv.z, s0.z, dp1 * shv.z);
    z4.w = fmaf(scv.w, s0.w, dp1 * shv.w);
    *(float4*)&g_z[(size_t)node * DIM + cc] = z4;

    if (layer > 0) {
        const float lw_prev = __ldg(&lwp[layer - 1]);
        float4 h;
        h.x = fmaf(un.x, scv.x, shv.x); h.y = fmaf(un.y, scv.y, shv.y);
        h.z = fmaf(un.z, scv.z, shv.z); h.w = fmaf(un.w, scv.w, shv.w);
        float4 a;
        if (layer == 1) {
            float lb = __ldg(lbp);
            a = make_float4(lb, lb, lb, lb);
        } else {
            a = *(const float4*)&g_acc[(size_t)node * DIM + cc];
        }
        a.x = fmaf(lw_prev, h.x, a.x); a.y = fmaf(lw_prev, h.y, a.y);
        a.z = fmaf(lw_prev, h.z, a.z); a.w = fmaf(lw_prev, h.w, a.w);
        *(float4*)&g_acc[(size_t)node * DIM + cc] = a;
    }
}

// ---------------- GIN MLP: u_next = relu(relu(z@W1+b1)@W2+b2) + stats ------
__global__ void __launch_bounds__(NT, 2)
gin_gemm_kernel(const float* __restrict__ w1, const float* __restrict__ b1,
                const float* __restrict__ w2, const float* __restrict__ b2,
                int rd) {
    extern __shared__ float sm[];
    float* sW = sm;
    float* sZ = sm + WREG;
    const int tid = threadIdx.x;
    const int rbase = blockIdx.x * 64;
    float* __restrict__ uout = g_u[rd ^ 1];

    for (int i = tid * 4; i < DIM * DIM; i += NT * 4)
        *(float4*)&sW[i] = *(const float4*)&w1[i];
    // coalesced z tile load: 64 rows x 128 cols
    for (int i = tid; i < 64 * 32; i += NT) {
        int r = i >> 5, c4 = (i & 31) << 2;
        int node = rbase + r;
        float4 z = make_float4(0, 0, 0, 0);
        if (node < N_NODES)
            z = *(const float4*)&g_z[(size_t)node * DIM + c4];
        *(float4*)&sZ[r * ZPAD + c4] = z;
    }
    __syncthreads();

    const int ty = tid >> 4, tx = tid & 15, c0 = tx << 3;
    ull acc[8][4];

    // ---- stage 1: T = relu(z @ W1 + b1) ----
    {
        ull b[4];
        #pragma unroll
        for (int j = 0; j < 4; j++)
            b[j] = pack2(b1[c0 + 2 * j], b1[c0 + 2 * j + 1]);
        #pragma unroll
        for (int i = 0; i < 8; i++)
            #pragma unroll
            for (int j = 0; j < 4; j++) acc[i][j] = b[j];
    }
    mma8<DIM, ZPAD>(sZ, sW, acc, ty, c0);
    __syncthreads();

    #pragma unroll
    for (int i = 0; i < 8; i++)
        #pragma unroll
        for (int j = 0; j < 4; j++) {
            float2 f = unpack2(acc[i][j]);
            sZ[(ty * 8 + i) * ZPAD + c0 + 2 * j]     = fmaxf(f.x, 0.0f);
            sZ[(ty * 8 + i) * ZPAD + c0 + 2 * j + 1] = fmaxf(f.y, 0.0f);
        }
    for (int i = tid * 4; i < DIM * DIM; i += NT * 4)
        *(float4*)&sW[i] = *(const float4*)&w2[i];
    __syncthreads();

    // ---- stage 2: u_next = relu(T @ W2 + b2) ----
    {
        ull b[4];
        #pragma unroll
        for (int j = 0; j < 4; j++)
            b[j] = pack2(b2[c0 + 2 * j], b2[c0 + 2 * j + 1]);
        #pragma unroll
        for (int i = 0; i < 8; i++)
            #pragma unroll
            for (int j = 0; j < 4; j++) acc[i][j] = b[j];
    }
    mma8<DIM, ZPAD>(sZ, sW, acc, ty, c0);
    __syncthreads();   // sZ reads done; reuse for stats partials

    float csum[8], csum2[8];
    #pragma unroll
    for (int j = 0; j < 8; j++) { csum[j] = 0.0f; csum2[j] = 0.0f; }
    #pragma unroll
    for (int i = 0; i < 8; i++) {
        int r = rbase + ty * 8 + i;
        float2 f0 = unpack2(acc[i][0]), f1 = unpack2(acc[i][1]);
        float2 f2 = unpack2(acc[i][2]), f3 = unpack2(acc[i][3]);
        float o[8] = { fmaxf(f0.x, 0.f), fmaxf(f0.y, 0.f),
                       fmaxf(f1.x, 0.f), fmaxf(f1.y, 0.f),
                       fmaxf(f2.x, 0.f), fmaxf(f2.y, 0.f),
                       fmaxf(f3.x, 0.f), fmaxf(f3.y, 0.f) };
        if (r < N_NODES) {
            *(float4*)&uout[(size_t)r * DIM + c0] =
                make_float4(o[0], o[1], o[2], o[3]);
            *(float4*)&uout[(size_t)r * DIM + c0 + 4] =
                make_float4(o[4], o[5], o[6], o[7]);
            #pragma unroll
            for (int j = 0; j < 8; j++) {
                csum[j] += o[j];
                csum2[j] += o[j] * o[j];
            }
        }
    }
    float* ps  = sZ;           // 8 x 128
    float* ps2 = sZ + 1024;    // 8 x 128
    #pragma unroll
    for (int j = 0; j < 8; j++) {
        ps [ty * DIM + c0 + j] = csum[j];
        ps2[ty * DIM + c0 + j] = csum2[j];
    }
    __syncthreads();
    {
        int col = tid;   // 128 threads, one column each, both kinds
        float t1 = 0.0f, t2 = 0.0f;
        #pragma unroll
        for (int t = 0; t < 8; t++) {
            t1 += ps [t * DIM + col];
            t2 += ps2[t * DIM + col];
        }
        atomicAdd(&g_stats[col], t1);
        atomicAdd(&g_stats[DIM + col], t2);
    }
}

// ---------------- final: BN(u3) + layer-conv + pool -------------------------
__global__ void final_kernel(const float* __restrict__ gamma,
                             const float* __restrict__ beta,
                             const float* __restrict__ lwp,
                             const int* __restrict__ batch,
                             float* __restrict__ out, int rd) {
    __shared__ float sSc[DIM], sSh[DIM];
    const int tid = threadIdx.x;
    if (tid < DIM) {
        float mean = g_stats[tid] * (1.0f / N_NODES);
        float var  = g_stats[DIM + tid] * (1.0f / N_NODES) - mean * mean;
        float sc = rsqrtf(var + BN_EPS) * gamma[tid];
        sSc[tid] = sc;
        sSh[tid] = beta[tid] - mean * sc;
    }
    __syncthreads();
    int gw = (blockIdx.x * blockDim.x + tid) >> 5;
    if (gw >= N_NODES) return;
    int lane = tid & 31, c4 = lane << 2;
    float lw3 = __ldg(&lwp[N_LAYERS - 1]);
    float4 u = *(const float4*)&g_u[rd][(size_t)gw * DIM + c4];
    float4 a = *(const float4*)&g_acc[(size_t)gw * DIM + c4];
    float4 h;
    h.x = fmaf(u.x, sSc[c4],     sSh[c4]);
    h.y = fmaf(u.y, sSc[c4 + 1], sSh[c4 + 1]);
    h.z = fmaf(u.z, sSc[c4 + 2], sSh[c4 + 2]);
    h.w = fmaf(u.w, sSc[c4 + 3], sSh[c4 + 3]);
    a.x = fmaf(lw3, h.x, a.x); a.y = fmaf(lw3, h.y, a.y);
    a.z = fmaf(lw3, h.z, a.z); a.w = fmaf(lw3, h.w, a.w);
    int b = __ldg(&batch[gw]);
    float* p = &out[b * DIM + c4];
    asm volatile("red.global.add.v4.f32 [%0], {%1,%2,%3,%4};"
                 :: "l"(p), "f"(a.x), "f"(a.y), "f"(a.z), "f"(a.w) : "memory");
}

// ---------------- launch ----------------------------------------------------
extern "C" void kernel_launch(void* const* d_in, const int* in_sizes, int n_in,
                              void* d_out, int out_size) {
    const float* x     = (const float*)d_in[0];
    const int*   ei    = (const int*)  d_in[1];
    const int*   batch = (const int*)  d_in[2];
    const float* iw1   = (const float*)d_in[3];
    const float* ib1   = (const float*)d_in[4];
    const float* iw2   = (const float*)d_in[5];
    const float* ib2   = (const float*)d_in[6];
    const float* gw1   = (const float*)d_in[7];
    const float* gb1   = (const float*)d_in[8];
    const float* gw2   = (const float*)d_in[9];
    const float* gb2   = (const float*)d_in[10];
    const float* gamma = (const float*)d_in[11];
    const float* beta  = (const float*)d_in[12];
    const float* lw    = (const float*)d_in[13];
    const float* lb    = (const float*)d_in[14];
    float* out = (float*)d_out;

    cudaFuncSetAttribute(ini_gemm_kernel,
                         cudaFuncAttributeMaxDynamicSharedMemorySize, SMEM_BYTES);
    cudaFuncSetAttribute(gin_gemm_kernel,
                         cudaFuncAttributeMaxDynamicSharedMemorySize, SMEM_BYTES);

    const int gemm_blocks = (N_NODES + 63) / 64;        // 782
    const int warp_blocks = (N_NODES * 32 + 255) / 256; // 6250
    const int fin_blocks  = warp_blocks;

    init_kernel<<<(N_GRAPHS * DIM + 255) / 256, 256>>>(out);     // 1
    count_kernel<<<(N_EDGES + 255) / 256, 256>>>(ei);            // 2
    scan_kernel<<<1, 1024>>>();                                  // 3
    ini_gemm_kernel<<<gemm_blocks, NT, SMEM_BYTES>>>(            // 4
        x, iw1, ib1, iw2, ib2);
    fill_kernel<<<(N_EDGES + 255) / 256, 256>>>(ei);             // 5

    for (int l = 0; l < N_LAYERS; l++) {
        const float* gm = gamma + (size_t)(l > 0 ? l - 1 : 0) * DIM;
        const float* bt = beta  + (size_t)(l > 0 ? l - 1 : 0) * DIM;
        prep_kernel<<<1, 128>>>(gm, bt, l);                      // 6 (l=0)
        gather_kernel<<<warp_blocks, 256>>>(lw, lb, l, l & 1);   // 7 (l=0)
        gin_gemm_kernel<<<gemm_blocks, NT, SMEM_BYTES>>>(
            gw1 + (size_t)l * DIM * DIM, gb1 + (size_t)l * DIM,
            gw2 + (size_t)l * DIM * DIM, gb2 + (size_t)l * DIM,
            l & 1);
    }

    final_kernel<<<fin_blocks, 256>>>(gamma + (size_t)(N_LAYERS - 1) * DIM,
                                      beta + (size_t)(N_LAYERS - 1) * DIM,
                                      lw, batch, out, 0);
}

// round 10
// speedup vs baseline: 1.3762x; 1.0346x over previous
#include <cuda_runtime.h>
#include <cstdint>

#define N_NODES 50000
#define N_EDGES 600000
#define N_GRAPHS 512
#define DIM 128
#define N_FEAT 78
#define N_LAYERS 4
#define BN_EPS 1e-5f

typedef unsigned long long ull;

// ---------------- scratch (device globals; no allocation allowed) ----------
__device__ float g_u[2][(size_t)N_NODES * DIM];  // ping-pong node features
__device__ float g_z[(size_t)N_NODES * DIM];     // gathered GIN input
__device__ float g_acc[(size_t)N_NODES * DIM];   // layer-conv accumulator
__device__ float g_stats[2][2 * DIM];            // double-buffered BN sums
__device__ int   g_deg[N_NODES];
__device__ int   g_ptr[N_NODES + 1];
__device__ int   g_cur[N_NODES];
__device__ int   g_csr[N_EDGES];                 // src sorted by dst

// ---------------- f32x2 packed-FMA helpers (FFMA2) -------------------------
__device__ __forceinline__ void fma2(ull& d, ull a, ull b) {
    asm("fma.rn.f32x2 %0, %1, %2, %0;" : "+l"(d) : "l"(a), "l"(b));
}
__device__ __forceinline__ ull bcast2(float x) {
    unsigned u = __float_as_uint(x);
    ull r; asm("mov.b64 %0, {%1, %1};" : "=l"(r) : "r"(u)); return r;
}
__device__ __forceinline__ ull pack2(float x, float y) {
    ull r; asm("mov.b64 %0, {%1, %2};" : "=l"(r)
               : "r"(__float_as_uint(x)), "r"(__float_as_uint(y))); return r;
}
__device__ __forceinline__ float2 unpack2(ull v) {
    unsigned lo, hi;
    asm("mov.b64 {%0, %1}, %2;" : "=r"(lo), "=r"(hi) : "l"(v));
    return make_float2(__uint_as_float(lo), __uint_as_float(hi));
}

// ---------------- 64-row GEMM micro-kernel, 8x8 thread tile ----------------
// 128 threads: ty = tid>>4 (8 row groups of 8), tx = tid&15 (8-col groups).
// sA pre-offset to the K-slice start; sW holds KSTEPS rows of W.
template <int KSTEPS, int APAD>
__device__ __forceinline__ void mma8(const float* __restrict__ sA,
                                     const float* __restrict__ sW,
                                     ull acc[8][4], int ty, int c0) {
    #pragma unroll 2
    for (int kk = 0; kk < KSTEPS; kk += 4) {
        float a[8][4];
        #pragma unroll
        for (int i = 0; i < 8; i++)
            *(float4*)a[i] = *(const float4*)&sA[(ty * 8 + i) * APAD + kk];
        #pragma unroll
        for (int k = 0; k < 4; k++) {
            const ulonglong2* wp = (const ulonglong2*)&sW[(kk + k) * DIM + c0];
            ulonglong2 w01 = wp[0], w23 = wp[1];
            #pragma unroll
            for (int i = 0; i < 8; i++) {
                ull av = bcast2(a[i][k]);
                fma2(acc[i][0], av, w01.x); fma2(acc[i][1], av, w01.y);
                fma2(acc[i][2], av, w23.x); fma2(acc[i][3], av, w23.y);
            }
        }
    }
}

#define ZPAD 132
#define XPAD 80
#define NT 128

// gin smem: W half (64x128) + Z tile (64xZPAD)
#define GIN_WH   (64 * DIM)                       // 8192 floats
#define SMEM_GIN ((GIN_WH + 64 * ZPAD) * (int)sizeof(float))   // 66560 B
// ini smem: W buf (40x128 max) + X tile (64xXPAD) + T tile (64xZPAD)
#define INI_WH   (40 * DIM)                       // 5120 floats
#define INI_X    (64 * XPAD)                      // 5120 floats
#define SMEM_INI ((INI_WH + INI_X + 64 * ZPAD) * (int)sizeof(float)) // 74752 B

// ---------------- CSR build --------------------------------------------------
__global__ void init_kernel(float* __restrict__ out) {
    int i = blockIdx.x * blockDim.x + threadIdx.x;
    if (i < N_NODES) g_deg[i] = 0;
    if (i < N_GRAPHS * DIM) out[i] = 0.0f;
}

__global__ void count_kernel(const int* __restrict__ ei) {
    int e = blockIdx.x * blockDim.x + threadIdx.x;
    if (e < N_EDGES) atomicAdd(&g_deg[__ldg(&ei[N_EDGES + e])], 1);
}

__global__ void scan_kernel() {
    __shared__ int ssum[1024];
    const int t = threadIdx.x;
    const int CH = (N_NODES + 1023) / 1024;   // 49
    const int base = t * CH;
    int sum = 0;
    for (int i = 0; i < CH; i++) {
        int idx = base + i;
        if (idx < N_NODES) sum += g_deg[idx];
    }
    ssum[t] = sum;
    __syncthreads();
    for (int off = 1; off < 1024; off <<= 1) {
        int v = (t >= off) ? ssum[t - off] : 0;
        __syncthreads();
        ssum[t] += v;
        __syncthreads();
    }
    int run = ssum[t] - sum;
    for (int i = 0; i < CH; i++) {
        int idx = base + i;
        if (idx < N_NODES) {
            g_ptr[idx] = run;
            g_cur[idx] = run;
            run += g_deg[idx];
        }
    }
    if (t == 0) g_ptr[N_NODES] = N_EDGES;
}

__global__ void fill_kernel(const int* __restrict__ ei) {
    int e = blockIdx.x * blockDim.x + threadIdx.x;
    if (e >= N_EDGES) return;
    int dst = __ldg(&ei[N_EDGES + e]);
    int pos = atomicAdd(&g_cur[dst], 1);
    g_csr[pos] = __ldg(&ei[e]);
}

// ---------------- ini embed: u0 = relu(x@W1+b1)@W2+b2 ----------------------
__global__ void __launch_bounds__(NT, 3)
ini_gemm_kernel(const float* __restrict__ x,
                const float* __restrict__ w1, const float* __restrict__ b1,
                const float* __restrict__ w2, const float* __restrict__ b2) {
    extern __shared__ float sm[];
    float* sW = sm;                  // 5120 floats: W slice
    float* sX = sm + INI_WH;         // 5120 floats: X tile (64 x XPAD)
    float* sT = sX + INI_X;          // 8448 floats: T tile (64 x ZPAD)
    const int tid = threadIdx.x;
    const int rbase = blockIdx.x * 64;

    for (int i = tid; i < 64 * XPAD; i += NT) {
        int r = i / XPAD, c = i - r * XPAD;
        sX[i] = (c < N_FEAT && rbase + r < N_NODES)
                ? x[(size_t)(rbase + r) * N_FEAT + c] : 0.0f;
    }

    const int ty = tid >> 4, tx = tid & 15, c0 = tx << 3;
    ull acc[8][4];

    // ---- stage 1: T = relu(x @ W1 + b1), 2 half-passes of 40 k-rows ----
    {
        ull b[4];
        #pragma unroll
        for (int j = 0; j < 4; j++)
            b[j] = pack2(b1[c0 + 2 * j], b1[c0 + 2 * j + 1]);
        #pragma unroll
        for (int i = 0; i < 8; i++)
            #pragma unroll
            for (int j = 0; j < 4; j++) acc[i][j] = b[j];
    }
    #pragma unroll 1
    for (int h = 0; h < 2; h++) {
        __syncthreads();           // sW free (and X tile ready for h=0)
        for (int i = tid * 4; i < 40 * DIM; i += NT * 4) {
            int gk = h * 40 * DIM + i;
            float4 v = make_float4(0, 0, 0, 0);
            if (gk < N_FEAT * DIM) v = *(const float4*)&w1[gk];
            *(float4*)&sW[i] = v;  // zero-fill padded k rows 78,79
        }
        __syncthreads();
        mma8<40, XPAD>(sX + h * 40, sW, acc, ty, c0);
    }
    __syncthreads();               // all stage-1 reads done

    #pragma unroll
    for (int i = 0; i < 8; i++)
        #pragma unroll
        for (int j = 0; j < 4; j++) {
            float2 f = unpack2(acc[i][j]);
            sT[(ty * 8 + i) * ZPAD + c0 + 2 * j]     = fmaxf(f.x, 0.0f);
            sT[(ty * 8 + i) * ZPAD + c0 + 2 * j + 1] = fmaxf(f.y, 0.0f);
        }

    // ---- stage 2: U = T @ W2 + b2, 4 quarter-passes of 32 k-rows ----
    {
        ull b[4];
        #pragma unroll
        for (int j = 0; j < 4; j++)
            b[j] = pack2(b2[c0 + 2 * j], b2[c0 + 2 * j + 1]);
        #pragma unroll
        for (int i = 0; i < 8; i++)
            #pragma unroll
            for (int j = 0; j < 4; j++) acc[i][j] = b[j];
    }
    #pragma unroll 1
    for (int q = 0; q < 4; q++) {
        __syncthreads();           // T writes visible (q=0); prev reads done
        for (int i = tid * 4; i < 32 * DIM; i += NT * 4)
            *(float4*)&sW[i] = *(const float4*)&w2[q * 32 * DIM + i];
        __syncthreads();
        mma8<32, ZPAD>(sT + q * 32, sW, acc, ty, c0);
    }

    #pragma unroll
    for (int i = 0; i < 8; i++) {
        int r = rbase + ty * 8 + i;
        if (r < N_NODES) {
            float2 f0 = unpack2(acc[i][0]), f1 = unpack2(acc[i][1]);
            float2 f2 = unpack2(acc[i][2]), f3 = unpack2(acc[i][3]);
            *(float4*)&g_u[0][(size_t)r * DIM + c0] =
                make_float4(f0.x, f0.y, f1.x, f1.y);
            *(float4*)&g_u[0][(size_t)r * DIM + c0 + 4] =
                make_float4(f2.x, f2.y, f3.x, f3.y);
        }
    }
}

// ---------------- gather: z = sc*(u+sum u_src)+(deg+1)*sh; acc += lw*h -----
// 1 warp per node; BN coefficients computed inline from prev-layer stats.
// Block 0 zeroes the stats buffer the following gemm will accumulate into.
__global__ void __launch_bounds__(256)
gather_kernel(const float* __restrict__ gamma, const float* __restrict__ beta,
              const float* __restrict__ lwp, const float* __restrict__ lbp,
              int layer, int rd) {
    if (blockIdx.x == 0 && threadIdx.x < 2 * DIM)
        g_stats[(layer + 1) & 1][threadIdx.x] = 0.0f;
    int node = (blockIdx.x * blockDim.x + threadIdx.x) >> 5;
    if (node >= N_NODES) return;
    const float* __restrict__ uin = g_u[rd];
    const int lane = threadIdx.x & 31, cc = lane << 2;

    float4 scv = make_float4(1, 1, 1, 1), shv = make_float4(0, 0, 0, 0);
    if (layer > 0) {
        const float* st = g_stats[layer & 1];
        float sc[4], sh[4];
        #pragma unroll
        for (int j = 0; j < 4; j++) {
            float mean = __ldg(&st[cc + j]) * (1.0f / N_NODES);
            float var  = __ldg(&st[DIM + cc + j]) * (1.0f / N_NODES)
                         - mean * mean;
            sc[j] = rsqrtf(var + BN_EPS) * __ldg(&gamma[cc + j]);
            sh[j] = __ldg(&beta[cc + j]) - mean * sc[j];
        }
        scv = make_float4(sc[0], sc[1], sc[2], sc[3]);
        shv = make_float4(sh[0], sh[1], sh[2], sh[3]);
    }

    float4 un = *(const float4*)&uin[(size_t)node * DIM + cc];
    int p0 = __ldg(&g_ptr[node]), p1 = __ldg(&g_ptr[node + 1]);
    float4 s0 = un, s1 = make_float4(0, 0, 0, 0);
    float4 s2 = make_float4(0, 0, 0, 0), s3 = make_float4(0, 0, 0, 0);
    int k = p0;
    for (; k + 4 <= p1; k += 4) {
        int sa = __ldg(&g_csr[k]),      sb = __ldg(&g_csr[k + 1]);
        int sc2 = __ldg(&g_csr[k + 2]), sd = __ldg(&g_csr[k + 3]);
        float4 ua = *(const float4*)&uin[(size_t)sa * DIM + cc];
        float4 ub = *(const float4*)&uin[(size_t)sb * DIM + cc];
        float4 uc = *(const float4*)&uin[(size_t)sc2 * DIM + cc];
        float4 ud = *(const float4*)&uin[(size_t)sd * DIM + cc];
        s0.x += ua.x; s0.y += ua.y; s0.z += ua.z; s0.w += ua.w;
        s1.x += ub.x; s1.y += ub.y; s1.z += ub.z; s1.w += ub.w;
        s2.x += uc.x; s2.y += uc.y; s2.z += uc.z; s2.w += uc.w;
        s3.x += ud.x; s3.y += ud.y; s3.z += ud.z; s3.w += ud.w;
    }
    for (; k < p1; k++) {
        int sa = __ldg(&g_csr[k]);
        float4 ua = *(const float4*)&uin[(size_t)sa * DIM + cc];
        s0.x += ua.x; s0.y += ua.y; s0.z += ua.z; s0.w += ua.w;
    }
    s0.x += s1.x + s2.x + s3.x; s0.y += s1.y + s2.y + s3.y;
    s0.z += s1.z + s2.z + s3.z; s0.w += s1.w + s2.w + s3.w;
    float dp1 = (float)(p1 - p0 + 1);
    float4 z4;
    z4.x = fmaf(scv.x, s0.x, dp1 * shv.x);
    z4.y = fmaf(scv.y, s0.y, dp1 * shv.y);
    z4.z = fmaf(scv.z, s0.z, dp1 * shv.z);
    z4.w = fmaf(scv.w, s0.w, dp1 * shv.w);
    *(float4*)&g_z[(size_t)node * DIM + cc] = z4;

    if (layer > 0) {
        const float lw_prev = __ldg(&lwp[layer - 1]);
        float4 h;
        h.x = fmaf(un.x, scv.x, shv.x); h.y = fmaf(un.y, scv.y, shv.y);
        h.z = fmaf(un.z, scv.z, shv.z); h.w = fmaf(un.w, scv.w, shv.w);
        float4 a;
        if (layer == 1) {
            float lb = __ldg(lbp);
            a = make_float4(lb, lb, lb, lb);
        } else {
            a = *(const float4*)&g_acc[(size_t)node * DIM + cc];
        }
        a.x = fmaf(lw_prev, h.x, a.x); a.y = fmaf(lw_prev, h.y, a.y);
        a.z = fmaf(lw_prev, h.z, a.z); a.w = fmaf(lw_prev, h.w, a.w);
        *(float4*)&g_acc[(size_t)node * DIM + cc] = a;
    }
}

// ---------------- GIN MLP: u_next = relu(relu(z@W1+b1)@W2+b2) + stats ------
__global__ void __launch_bounds__(NT, 3)
gin_gemm_kernel(const float* __restrict__ w1, const float* __restrict__ b1,
                const float* __restrict__ w2, const float* __restrict__ b2,
                int rd, int sout) {
    extern __shared__ float sm[];
    float* sW = sm;                  // 8192 floats: W half (64 rows)
    float* sZ = sm + GIN_WH;         // 8448 floats: Z / T / stats partials
    const int tid = threadIdx.x;
    const int rbase = blockIdx.x * 64;
    float* __restrict__ uout = g_u[rd ^ 1];
    float* __restrict__ stats = g_stats[sout];

    // coalesced z tile load: 64 rows x 128 cols
    for (int i = tid; i < 64 * 32; i += NT) {
        int r = i >> 5, c4 = (i & 31) << 2;
        int node = rbase + r;
        float4 z = make_float4(0, 0, 0, 0);
        if (node < N_NODES)
            z = *(const float4*)&g_z[(size_t)node * DIM + c4];
        *(float4*)&sZ[r * ZPAD + c4] = z;
    }

    const int ty = tid >> 4, tx = tid & 15, c0 = tx << 3;
    ull acc[8][4];

    // ---- stage 1: T = relu(z @ W1 + b1), 2 half-passes ----
    {
        ull b[4];
        #pragma unroll
        for (int j = 0; j < 4; j++)
            b[j] = pack2(b1[c0 + 2 * j], b1[c0 + 2 * j + 1]);
        #pragma unroll
        for (int i = 0; i < 8; i++)
            #pragma unroll
            for (int j = 0; j < 4; j++) acc[i][j] = b[j];
    }
    #pragma unroll 1
    for (int h = 0; h < 2; h++) {
        __syncthreads();           // Z tile ready (h=0) / sW free (h=1)
        for (int i = tid * 4; i < 64 * DIM; i += NT * 4)
            *(float4*)&sW[i] = *(const float4*)&w1[h * 64 * DIM + i];
        __syncthreads();
        mma8<64, ZPAD>(sZ + h * 64, sW, acc, ty, c0);
    }
    __syncthreads();               // all stage-1 reads of sZ/sW done

    #pragma unroll
    for (int i = 0; i < 8; i++)
        #pragma unroll
        for (int j = 0; j < 4; j++) {
            float2 f = unpack2(acc[i][j]);
            sZ[(ty * 8 + i) * ZPAD + c0 + 2 * j]     = fmaxf(f.x, 0.0f);
            sZ[(ty * 8 + i) * ZPAD + c0 + 2 * j + 1] = fmaxf(f.y, 0.0f);
        }

    // ---- stage 2: u_next = relu(T @ W2 + b2), 2 half-passes ----
    {
        ull b[4];
        #pragma unroll
        for (int j = 0; j < 4; j++)
            b[j] = pack2(b2[c0 + 2 * j], b2[c0 + 2 * j + 1]);
        #pragma unroll
        for (int i = 0; i < 8; i++)
            #pragma unroll
            for (int j = 0; j < 4; j++) acc[i][j] = b[j];
    }
    #pragma unroll 1
    for (int h = 0; h < 2; h++) {
        __syncthreads();           // T writes visible / prev reads done
        for (int i = tid * 4; i < 64 * DIM; i += NT * 4)
            *(float4*)&sW[i] = *(const float4*)&w2[h * 64 * DIM + i];
        __syncthreads();
        mma8<64, ZPAD>(sZ + h * 64, sW, acc, ty, c0);
    }
    __syncthreads();               // sZ reads done; reuse for stats partials

    float csum[8], csum2[8];
    #pragma unroll
    for (int j = 0; j < 8; j++) { csum[j] = 0.0f; csum2[j] = 0.0f; }
    #pragma unroll
    for (int i = 0; i < 8; i++) {
        int r = rbase + ty * 8 + i;
        float2 f0 = unpack2(acc[i][0]), f1 = unpack2(acc[i][1]);
        float2 f2 = unpack2(acc[i][2]), f3 = unpack2(acc[i][3]);
        float o[8] = { fmaxf(f0.x, 0.f), fmaxf(f0.y, 0.f),
                       fmaxf(f1.x, 0.f), fmaxf(f1.y, 0.f),
                       fmaxf(f2.x, 0.f), fmaxf(f2.y, 0.f),
                       fmaxf(f3.x, 0.f), fmaxf(f3.y, 0.f) };
        if (r < N_NODES) {
            *(float4*)&uout[(size_t)r * DIM + c0] =
                make_float4(o[0], o[1], o[2], o[3]);
            *(float4*)&uout[(size_t)r * DIM + c0 + 4] =
                make_float4(o[4], o[5], o[6], o[7]);
            #pragma unroll
            for (int j = 0; j < 8; j++) {
                csum[j] += o[j];
                csum2[j] += o[j] * o[j];
            }
        }
    }
    float* ps  = sZ;           // 8 x 128
    float* ps2 = sZ + 1024;    // 8 x 128
    #pragma unroll
    for (int j = 0; j < 8; j++) {
        ps [ty * DIM + c0 + j] = csum[j];
        ps2[ty * DIM + c0 + j] = csum2[j];
    }
    __syncthreads();
    {
        int col = tid;   // 128 threads, one column each, both kinds
        float t1 = 0.0f, t2 = 0.0f;
        #pragma unroll
        for (int t = 0; t < 8; t++) {
            t1 += ps [t * DIM + col];
            t2 += ps2[t * DIM + col];
        }
        atomicAdd(&stats[col], t1);
        atomicAdd(&stats[DIM + col], t2);
    }
}

// ---------------- final: BN(u3) + layer-conv + pool -------------------------
__global__ void final_kernel(const float* __restrict__ gamma,
                             const float* __restrict__ beta,
                             const float* __restrict__ lwp,
                             const int* __restrict__ batch,
                             float* __restrict__ out, int rd) {
    __shared__ float sSc[DIM], sSh[DIM];
    const int tid = threadIdx.x;
    if (tid < DIM) {
        float mean = g_stats[0][tid] * (1.0f / N_NODES);
        float var  = g_stats[0][DIM + tid] * (1.0f / N_NODES) - mean * mean;
        float sc = rsqrtf(var + BN_EPS) * gamma[tid];
        sSc[tid] = sc;
        sSh[tid] = beta[tid] - mean * sc;
    }
    __syncthreads();
    int gw = (blockIdx.x * blockDim.x + tid) >> 5;
    if (gw >= N_NODES) return;
    int lane = tid & 31, c4 = lane << 2;
    float lw3 = __ldg(&lwp[N_LAYERS - 1]);
    float4 u = *(const float4*)&g_u[rd][(size_t)gw * DIM + c4];
    float4 a = *(const float4*)&g_acc[(size_t)gw * DIM + c4];
    float4 h;
    h.x = fmaf(u.x, sSc[c4],     sSh[c4]);
    h.y = fmaf(u.y, sSc[c4 + 1], sSh[c4 + 1]);
    h.z = fmaf(u.z, sSc[c4 + 2], sSh[c4 + 2]);
    h.w = fmaf(u.w, sSc[c4 + 3], sSh[c4 + 3]);
    a.x = fmaf(lw3, h.x, a.x); a.y = fmaf(lw3, h.y, a.y);
    a.z = fmaf(lw3, h.z, a.z); a.w = fmaf(lw3, h.w, a.w);
    int b = __ldg(&batch[gw]);
    float* p = &out[b * DIM + c4];
    asm volatile("red.global.add.v4.f32 [%0], {%1,%2,%3,%4};"
                 :: "l"(p), "f"(a.x), "f"(a.y), "f"(a.z), "f"(a.w) : "memory");
}

// ---------------- launch ----------------------------------------------------
extern "C" void kernel_launch(void* const* d_in, const int* in_sizes, int n_in,
                              void* d_out, int out_size) {
    const float* x     = (const float*)d_in[0];
    const int*   ei    = (const int*)  d_in[1];
    const int*   batch = (const int*)  d_in[2];
    const float* iw1   = (const float*)d_in[3];
    const float* ib1   = (const float*)d_in[4];
    const float* iw2   = (const float*)d_in[5];
    const float* ib2   = (const float*)d_in[6];
    const float* gw1   = (const float*)d_in[7];
    const float* gb1   = (const float*)d_in[8];
    const float* gw2   = (const float*)d_in[9];
    const float* gb2   = (const float*)d_in[10];
    const float* gamma = (const float*)d_in[11];
    const float* beta  = (const float*)d_in[12];
    const float* lw    = (const float*)d_in[13];
    const float* lb    = (const float*)d_in[14];
    float* out = (float*)d_out;

    cudaFuncSetAttribute(ini_gemm_kernel,
                         cudaFuncAttributeMaxDynamicSharedMemorySize, SMEM_INI);
    cudaFuncSetAttribute(gin_gemm_kernel,
                         cudaFuncAttributeMaxDynamicSharedMemorySize, SMEM_GIN);

    const int gemm_blocks = (N_NODES + 63) / 64;        // 782
    const int warp_blocks = (N_NODES * 32 + 255) / 256; // 6250

    init_kernel<<<(N_GRAPHS * DIM + 255) / 256, 256>>>(out);     // 1
    count_kernel<<<(N_EDGES + 255) / 256, 256>>>(ei);            // 2
    scan_kernel<<<1, 1024>>>();                                  // 3
    ini_gemm_kernel<<<gemm_blocks, NT, SMEM_INI>>>(              // 4 (profiled)
        x, iw1, ib1, iw2, ib2);
    fill_kernel<<<(N_EDGES + 255) / 256, 256>>>(ei);             // 5

    for (int l = 0; l < N_LAYERS; l++) {
        const float* gm = gamma + (size_t)(l > 0 ? l - 1 : 0) * DIM;
        const float* bt = beta  + (size_t)(l > 0 ? l - 1 : 0) * DIM;
        gather_kernel<<<warp_blocks, 256>>>(gm, bt, lw, lb, l, l & 1);
        gin_gemm_kernel<<<gemm_blocks, NT, SMEM_GIN>>>(
            gw1 + (size_t)l * DIM * DIM, gb1 + (size_t)l * DIM,
            gw2 + (size_t)l * DIM * DIM, gb2 + (size_t)l * DIM,
            l & 1, (l + 1) & 1);
    }

    final_kernel<<<warp_blocks, 256>>>(gamma + (size_t)(N_LAYERS - 1) * DIM,
                                       beta + (size_t)(N_LAYERS - 1) * DIM,
                                       lw, batch, out, 0);
}